// round 8
// baseline (speedup 1.0000x reference)
#include <cuda_runtime.h>
#include <cstdint>

// Problem dims
#define PD1   128
#define PD2   128
#define PB    16
#define PSIN  64
#define PSOUT 128
// a / h layout: [i][j][b][s] row-major, s fastest.
// float offset = i*262144 + j*2048 + b*128 + s

typedef unsigned long long ull_t;

__device__ __forceinline__ ull_t pack2(float x) {
    unsigned int xi = __float_as_uint(x);
    ull_t r;
    asm("mov.b64 %0, {%1, %1};" : "=l"(r) : "r"(xi));
    return r;
}
__device__ __forceinline__ void ffma2(ull_t &d, ull_t a, ull_t b) {
    asm("fma.rn.f32x2 %0, %1, %2, %0;" : "+l"(d) : "l"(a), "l"(b));
}
__device__ __forceinline__ float tanh_fast(float z) {
    // tanh(z) = 1 - 2/(exp(2z)+1) via MUFU ex2 + rcp (err ~1e-6)
    float e;
    asm("ex2.approx.f32 %0, %1;" : "=f"(e) : "f"(z * 2.8853900817779268f));
    float rc;
    asm("rcp.approx.f32 %0, %1;" : "=f"(rc) : "f"(e + 1.0f));
    return fmaf(-2.0f, rc, 1.0f);
}

// ---------------- Kernel 1: a = x @ w + bias  (into d_out) ----------------
// Measured ~92us: 128m x 128n tile, 256 threads, micro-tile 8m x 8n
// (4 f32x2 segs), K=64 in two 32-wide phases. Unchanged from R7.
#define XS_LD 36
__global__ __launch_bounds__(256)
void mdrnn_gemm_kernel(const float* __restrict__ X, const float* __restrict__ W,
                       const float* __restrict__ Bias, float* __restrict__ A) {
    __shared__ float xs[128 * XS_LD];   // 18432 B
    __shared__ float ws[32 * 128];      // 16384 B

    const int tid   = threadIdx.x;
    const int mtile = blockIdx.x;                 // 2048 tiles of 128 rows
    const float* Xb = X + (size_t)mtile * 128 * PSIN;

    const int tidm = tid >> 4;
    const int tidn = tid & 15;
    const int m0   = tidm * 8;
    const int n0   = tidn * 2;

    ull_t acc[8][4];
#pragma unroll
    for (int mi = 0; mi < 8; mi++)
#pragma unroll
        for (int seg = 0; seg < 4; seg++) acc[mi][seg] = 0ULL;

    for (int kk = 0; kk < PSIN; kk += 32) {
        __syncthreads();
#pragma unroll
        for (int q = 0; q < 4; q++) {
            int id  = tid + 256 * q;
            int row = id >> 3;
            int kq  = id & 7;
            *(float4*)&xs[row * XS_LD + kq * 4] =
                *(const float4*)(Xb + row * PSIN + kk + kq * 4);
        }
#pragma unroll
        for (int q = 0; q < 4; q++) {
            int id = tid + 256 * q;
            int k  = id >> 5;
            int nq = id & 31;
            *(float4*)&ws[k * 128 + nq * 4] =
                *(const float4*)(W + (size_t)(kk + k) * PSOUT + nq * 4);
        }
        __syncthreads();

#pragma unroll 4
        for (int k = 0; k < 32; k++) {
            ull_t wv[4];
#pragma unroll
            for (int seg = 0; seg < 4; seg++)
                wv[seg] = *(const ull_t*)&ws[k * 128 + n0 + seg * 32];
#pragma unroll
            for (int mi = 0; mi < 8; mi++) {
                ull_t xp = pack2(xs[(m0 + mi) * XS_LD + k]);
#pragma unroll
                for (int seg = 0; seg < 4; seg++) ffma2(acc[mi][seg], xp, wv[seg]);
            }
        }
    }

    float2 bv[4];
#pragma unroll
    for (int seg = 0; seg < 4; seg++)
        bv[seg] = *(const float2*)(Bias + n0 + seg * 32);

#pragma unroll
    for (int mi = 0; mi < 8; mi++) {
        float* out = A + ((size_t)mtile * 128 + m0 + mi) * PSOUT;
#pragma unroll
        for (int seg = 0; seg < 4; seg++) {
            uint2 u = *(uint2*)&acc[mi][seg];
            float2 o;
            o.x = __uint_as_float(u.x) + bv[seg].x;
            o.y = __uint_as_float(u.y) + bv[seg].y;
            *(float2*)(out + n0 + seg * 32) = o;
        }
    }
}

// ---------------- Kernel 2: pipelined warp-wavefront scan ----------------
// 256 blocks x 128 threads. One block per (b, 8-s chunk); WARP w owns strip
// rows [32w, 32w+32). Within a warp: rows on lanes, diagonal skew
// (iter t: lane l does j = t - l; h[i-1][j] via shfl_up of prev iter's h).
// Strip boundary handed warp w -> w+1 column-by-column through smem buf with
// an acquire/release progress counter: producer lane 31 stores buf[w][j] then
// st.release prog[w]=j+1; consumer lane 0 spins on ld.acquire prog[w-1] > j.
// Warp w+1 trails warp w by 31 columns -> all 4 warps concurrent.
// Prefetch ring depth 8, STATIC indices (unroll 8); refill guarded only by jf.
#define SDEPTH 8
__global__ __launch_bounds__(128)
void mdrnn_scan_kernel(const float* __restrict__ U, float* __restrict__ H) {
    __shared__ float4 buf[3][128][2];   // boundary rows of warps 0..2, 12KB
    __shared__ int    prog[4];          // columns completed by warp w

    const int lane = threadIdx.x & 31;
    const int warp = threadIdx.x >> 5;       // strip index 0..3
    const int b    = blockIdx.x >> 4;        // 0..15
    const int sc   = blockIdx.x & 15;        // 0..15
    const int s0   = sc * 8;

    if (threadIdx.x < 4) prog[threadIdx.x] = 0;
    __syncthreads();

    const float4 u0a = *(const float4*)(U + s0);
    const float4 u0b = *(const float4*)(U + s0 + 4);
    const float4 u1a = *(const float4*)(U + PSOUT + s0);
    const float4 u1b = *(const float4*)(U + PSOUT + s0 + 4);

    const int row = warp * 32 + lane;
    float* Hrow = H + (size_t)row * 262144 + (size_t)b * PSOUT + s0;  // + j*2048

    const uint32_t progPrevA =
        (uint32_t)__cvta_generic_to_shared(&prog[warp > 0 ? warp - 1 : 0]);
    const uint32_t progSelfA = (uint32_t)__cvta_generic_to_shared(&prog[warp]);

    // seed ring: slot q <- a[j = q - lane] (consumed at t = q)
    float4 ra[SDEPTH], rb[SDEPTH];
#pragma unroll
    for (int q = 0; q < SDEPTH; q++) {
        int j = q - lane;
        if ((unsigned)j < 128u) {
            ra[q] = *(const float4*)(Hrow + (size_t)j * 2048);
            rb[q] = *(const float4*)(Hrow + (size_t)j * 2048 + 4);
        }
    }

    float4 ha = make_float4(0.f, 0.f, 0.f, 0.f);
    float4 hb = make_float4(0.f, 0.f, 0.f, 0.f);

#pragma unroll 8
    for (int t = 0; t < 160; t++) {
        // cross-lane handoff of previous iteration's h
        float4 pa, pb;
        pa.x = __shfl_up_sync(0xffffffffu, ha.x, 1);
        pa.y = __shfl_up_sync(0xffffffffu, ha.y, 1);
        pa.z = __shfl_up_sync(0xffffffffu, ha.z, 1);
        pa.w = __shfl_up_sync(0xffffffffu, ha.w, 1);
        pb.x = __shfl_up_sync(0xffffffffu, hb.x, 1);
        pb.y = __shfl_up_sync(0xffffffffu, hb.y, 1);
        pb.z = __shfl_up_sync(0xffffffffu, hb.z, 1);
        pb.w = __shfl_up_sync(0xffffffffu, hb.w, 1);

        const int j    = t - lane;
        const int slot = t & (SDEPTH - 1);   // static under unroll 8

        // consume slot, refill independent of this iter's activity
        float4 aa = ra[slot], ab = rb[slot];
        int jf = t + SDEPTH - lane;
        if ((unsigned)jf < 128u) {
            ra[slot] = *(const float4*)(Hrow + (size_t)jf * 2048);
            rb[slot] = *(const float4*)(Hrow + (size_t)jf * 2048 + 4);
        }

        if ((unsigned)j < 128u) {
            float4 qa, qb;   // h[row-1][j]
            if (lane == 0) {
                if (warp == 0) {
                    qa = make_float4(0.f, 0.f, 0.f, 0.f);
                    qb = make_float4(0.f, 0.f, 0.f, 0.f);
                } else {
                    int p;
                    do {
                        asm volatile("ld.acquire.cta.shared.b32 %0, [%1];"
                                     : "=r"(p) : "r"(progPrevA));
                    } while (p <= j);
                    qa = buf[warp - 1][j][0];
                    qb = buf[warp - 1][j][1];
                }
            } else {
                qa = pa; qb = pb;
            }

            float4 za, zb;
            za.x = fmaf(qa.x, u0a.x, aa.x); za.x = fmaf(ha.x, u1a.x, za.x);
            za.y = fmaf(qa.y, u0a.y, aa.y); za.y = fmaf(ha.y, u1a.y, za.y);
            za.z = fmaf(qa.z, u0a.z, aa.z); za.z = fmaf(ha.z, u1a.z, za.z);
            za.w = fmaf(qa.w, u0a.w, aa.w); za.w = fmaf(ha.w, u1a.w, za.w);
            zb.x = fmaf(qb.x, u0b.x, ab.x); zb.x = fmaf(hb.x, u1b.x, zb.x);
            zb.y = fmaf(qb.y, u0b.y, ab.y); zb.y = fmaf(hb.y, u1b.y, zb.y);
            zb.z = fmaf(qb.z, u0b.z, ab.z); zb.z = fmaf(hb.z, u1b.z, zb.z);
            zb.w = fmaf(qb.w, u0b.w, ab.w); zb.w = fmaf(hb.w, u1b.w, zb.w);

            ha.x = tanh_fast(za.x); ha.y = tanh_fast(za.y);
            ha.z = tanh_fast(za.z); ha.w = tanh_fast(za.w);
            hb.x = tanh_fast(zb.x); hb.y = tanh_fast(zb.y);
            hb.z = tanh_fast(zb.z); hb.w = tanh_fast(zb.w);

            *(float4*)(Hrow + (size_t)j * 2048)     = ha;
            *(float4*)(Hrow + (size_t)j * 2048 + 4) = hb;

            if (lane == 31 && warp < 3) {
                buf[warp][j][0] = ha;
                buf[warp][j][1] = hb;
                asm volatile("st.release.cta.shared.b32 [%0], %1;"
                             :: "r"(progSelfA), "r"(j + 1) : "memory");
            }
        }
    }
}

// ---------------- launch ----------------
extern "C" void kernel_launch(void* const* d_in, const int* in_sizes, int n_in,
                              void* d_out, int out_size) {
    const float* X    = (const float*)d_in[0];   // (128,128,16,64)
    const float* W    = (const float*)d_in[1];   // (64,128)
    const float* U    = (const float*)d_in[2];   // (2,128)
    const float* Bias = (const float*)d_in[3];   // (128,)
    float* H = (float*)d_out;                    // (128,128,16,128) — holds a, then h

    (void)in_sizes; (void)n_in; (void)out_size;

    mdrnn_gemm_kernel<<<2048, 256>>>(X, W, Bias, H);
    mdrnn_scan_kernel<<<256, 128>>>(U, H);
}

// round 9
// speedup vs baseline: 2.5263x; 2.5263x over previous
#include <cuda_runtime.h>
#include <cstdint>

// Problem dims
#define PD1   128
#define PD2   128
#define PB    16
#define PSIN  64
#define PSOUT 128
// a / h layout: [i][j][b][s] row-major, s fastest.
// float offset = i*262144 + j*2048 + b*128 + s

typedef unsigned long long ull_t;

__device__ __forceinline__ ull_t pack2(float x) {
    unsigned int xi = __float_as_uint(x);
    ull_t r;
    asm("mov.b64 %0, {%1, %1};" : "=l"(r) : "r"(xi));
    return r;
}
__device__ __forceinline__ void ffma2(ull_t &d, ull_t a, ull_t b) {
    asm("fma.rn.f32x2 %0, %1, %2, %0;" : "+l"(d) : "l"(a), "l"(b));
}
__device__ __forceinline__ float tanh_fast(float z) {
    // tanh(z) = 1 - 2/(exp(2z)+1) via MUFU ex2 + rcp (err ~1e-6)
    float e;
    asm("ex2.approx.f32 %0, %1;" : "=f"(e) : "f"(z * 2.8853900817779268f));
    float rc;
    asm("rcp.approx.f32 %0, %1;" : "=f"(rc) : "f"(e + 1.0f));
    return fmaf(-2.0f, rc, 1.0f);
}

// ---------------- Kernel 1: a = x @ w + bias  (into d_out) ----------------
// Measured ~92us: 128m x 128n tile, 256 threads, micro-tile 8m x 8n
// (4 f32x2 segs), K=64 in two 32-wide phases. Unchanged.
#define XS_LD 36
__global__ __launch_bounds__(256)
void mdrnn_gemm_kernel(const float* __restrict__ X, const float* __restrict__ W,
                       const float* __restrict__ Bias, float* __restrict__ A) {
    __shared__ float xs[128 * XS_LD];   // 18432 B
    __shared__ float ws[32 * 128];      // 16384 B

    const int tid   = threadIdx.x;
    const int mtile = blockIdx.x;                 // 2048 tiles of 128 rows
    const float* Xb = X + (size_t)mtile * 128 * PSIN;

    const int tidm = tid >> 4;
    const int tidn = tid & 15;
    const int m0   = tidm * 8;
    const int n0   = tidn * 2;

    ull_t acc[8][4];
#pragma unroll
    for (int mi = 0; mi < 8; mi++)
#pragma unroll
        for (int seg = 0; seg < 4; seg++) acc[mi][seg] = 0ULL;

    for (int kk = 0; kk < PSIN; kk += 32) {
        __syncthreads();
#pragma unroll
        for (int q = 0; q < 4; q++) {
            int id  = tid + 256 * q;
            int row = id >> 3;
            int kq  = id & 7;
            *(float4*)&xs[row * XS_LD + kq * 4] =
                *(const float4*)(Xb + row * PSIN + kk + kq * 4);
        }
#pragma unroll
        for (int q = 0; q < 4; q++) {
            int id = tid + 256 * q;
            int k  = id >> 5;
            int nq = id & 31;
            *(float4*)&ws[k * 128 + nq * 4] =
                *(const float4*)(W + (size_t)(kk + k) * PSOUT + nq * 4);
        }
        __syncthreads();

#pragma unroll 4
        for (int k = 0; k < 32; k++) {
            ull_t wv[4];
#pragma unroll
            for (int seg = 0; seg < 4; seg++)
                wv[seg] = *(const ull_t*)&ws[k * 128 + n0 + seg * 32];
#pragma unroll
            for (int mi = 0; mi < 8; mi++) {
                ull_t xp = pack2(xs[(m0 + mi) * XS_LD + k]);
#pragma unroll
                for (int seg = 0; seg < 4; seg++) ffma2(acc[mi][seg], xp, wv[seg]);
            }
        }
    }

    float2 bv[4];
#pragma unroll
    for (int seg = 0; seg < 4; seg++)
        bv[seg] = *(const float2*)(Bias + n0 + seg * 32);

#pragma unroll
    for (int mi = 0; mi < 8; mi++) {
        float* out = A + ((size_t)mtile * 128 + m0 + mi) * PSOUT;
#pragma unroll
        for (int seg = 0; seg < 4; seg++) {
            uint2 u = *(uint2*)&acc[mi][seg];
            float2 o;
            o.x = __uint_as_float(u.x) + bv[seg].x;
            o.y = __uint_as_float(u.y) + bv[seg].y;
            *(float2*)(out + n0 + seg * 32) = o;
        }
    }
}

// ---------------- Kernel 2: 4-warp block wavefront scan ----------------
// 256 blocks x 128 threads. Block = one (b, 8-wide s chunk); thread = row i
// (i = tid, 0..127) holding 8 s values as 2 float4 (one full 32B sector).
// 256 diagonal steps; at step t thread i handles j = t - i.
// h[i-1][j] exchange via double-buffered smem + __syncthreads (4-warp
// barrier ~tens of cycles, vs R1's 32-warp ~1000cyc/step).
// Prefetch ring depth 8, STATIC indices (unroll 8 makes t&7 constant);
// refill guarded only by jf validity (activity-independent).
#define SDEPTH 8
__global__ __launch_bounds__(128)
void mdrnn_scan_kernel(const float* __restrict__ U, float* __restrict__ H) {
    __shared__ float4 sha[2][128];
    __shared__ float4 shb[2][128];

    const int tid = threadIdx.x;            // row i
    const int b   = blockIdx.x >> 4;        // 0..15
    const int sc  = blockIdx.x & 15;        // 0..15
    const int s0  = sc * 8;

    const float4 u0a = *(const float4*)(U + s0);
    const float4 u0b = *(const float4*)(U + s0 + 4);
    const float4 u1a = *(const float4*)(U + PSOUT + s0);
    const float4 u1b = *(const float4*)(U + PSOUT + s0 + 4);

    float* Hrow = H + (size_t)tid * 262144 + (size_t)b * PSOUT + s0;  // + j*2048

    // seed ring: slot q <- a[j = q - tid] (consumed at t = q), valid j only
    float4 ra[SDEPTH], rb[SDEPTH];
#pragma unroll
    for (int q = 0; q < SDEPTH; q++) {
        int j = q - tid;
        if ((unsigned)j < 128u) {
            ra[q] = *(const float4*)(Hrow + (size_t)j * 2048);
            rb[q] = *(const float4*)(Hrow + (size_t)j * 2048 + 4);
        }
    }

    float4 ha = make_float4(0.f, 0.f, 0.f, 0.f);   // this row's h, prev column
    float4 hb = make_float4(0.f, 0.f, 0.f, 0.f);

#pragma unroll 8
    for (int t = 0; t < 256; t++) {
        const int j    = t - tid;
        const int slot = t & (SDEPTH - 1);   // static under unroll 8

        // consume slot, refill independent of this iter's activity
        float4 aa = ra[slot], ab = rb[slot];
        int jf = t + SDEPTH - tid;
        if ((unsigned)jf < 128u) {
            ra[slot] = *(const float4*)(Hrow + (size_t)jf * 2048);
            rb[slot] = *(const float4*)(Hrow + (size_t)jf * 2048 + 4);
        }

        if ((unsigned)j < 128u) {
            float4 qa, qb;   // h[i-1][j] (written by thread tid-1 last step)
            if (tid == 0) {
                qa = make_float4(0.f, 0.f, 0.f, 0.f);
                qb = make_float4(0.f, 0.f, 0.f, 0.f);
            } else {
                qa = sha[(t & 1) ^ 1][tid - 1];
                qb = shb[(t & 1) ^ 1][tid - 1];
            }

            float4 za, zb;
            za.x = fmaf(qa.x, u0a.x, aa.x); za.x = fmaf(ha.x, u1a.x, za.x);
            za.y = fmaf(qa.y, u0a.y, aa.y); za.y = fmaf(ha.y, u1a.y, za.y);
            za.z = fmaf(qa.z, u0a.z, aa.z); za.z = fmaf(ha.z, u1a.z, za.z);
            za.w = fmaf(qa.w, u0a.w, aa.w); za.w = fmaf(ha.w, u1a.w, za.w);
            zb.x = fmaf(qb.x, u0b.x, ab.x); zb.x = fmaf(hb.x, u1b.x, zb.x);
            zb.y = fmaf(qb.y, u0b.y, ab.y); zb.y = fmaf(hb.y, u1b.y, zb.y);
            zb.z = fmaf(qb.z, u0b.z, ab.z); zb.z = fmaf(hb.z, u1b.z, zb.z);
            zb.w = fmaf(qb.w, u0b.w, ab.w); zb.w = fmaf(hb.w, u1b.w, zb.w);

            ha.x = tanh_fast(za.x); ha.y = tanh_fast(za.y);
            ha.z = tanh_fast(za.z); ha.w = tanh_fast(za.w);
            hb.x = tanh_fast(zb.x); hb.y = tanh_fast(zb.y);
            hb.z = tanh_fast(zb.z); hb.w = tanh_fast(zb.w);

            sha[t & 1][tid] = ha;
            shb[t & 1][tid] = hb;
            *(float4*)(Hrow + (size_t)j * 2048)     = ha;
            *(float4*)(Hrow + (size_t)j * 2048 + 4) = hb;
        }
        __syncthreads();
    }
}

// ---------------- launch ----------------
extern "C" void kernel_launch(void* const* d_in, const int* in_sizes, int n_in,
                              void* d_out, int out_size) {
    const float* X    = (const float*)d_in[0];   // (128,128,16,64)
    const float* W    = (const float*)d_in[1];   // (64,128)
    const float* U    = (const float*)d_in[2];   // (2,128)
    const float* Bias = (const float*)d_in[3];   // (128,)
    float* H = (float*)d_out;                    // (128,128,16,128) — holds a, then h

    (void)in_sizes; (void)n_in; (void)out_size;

    mdrnn_gemm_kernel<<<2048, 256>>>(X, W, Bias, H);
    mdrnn_scan_kernel<<<256, 128>>>(U, H);
}